// round 10
// baseline (speedup 1.0000x reference)
#include <cuda_runtime.h>
#include <cuda_bf16.h>
#include <stdint.h>
#include <math.h>

// Problem dims
#define BB 2048
#define SS 32
#define DD 1024
#define PP 16
#define FF 512
#define HH 512

// ---------------- scratch layout (single __device__ array) ------------------
#define N_T1    ((size_t)BB * SS * DD)
#define N_H     ((size_t)BB * SS * HH)
#define N_ATTN  ((size_t)BB * SS * SS)
#define N_GV    ((size_t)BB * SS)
#define N_DAV   ((size_t)BB * SS)
#define N_AVMIX ((size_t)2 * BB * DD)
#define N_AVPRE ((size_t)2 * BB * DD)
#define N_FAV   ((size_t)3 * BB * DD)
#define N_HEAD  ((size_t)3 * BB * FF)
#define N_MT    ((size_t)DD * DD)
#define N_WT    ((size_t)2 * DD * DD)

#define OF_T1    ((size_t)0)
#define OF_H     (OF_T1 + N_T1)
#define OF_ATTN  (OF_H + N_H)
#define OF_GV    (OF_ATTN + N_ATTN)
#define OF_DAV   (OF_GV + N_GV)
#define OF_AVMIX (OF_DAV + N_DAV)
#define OF_AVPRE (OF_AVMIX + N_AVMIX)
#define OF_FAV   (OF_AVPRE + N_AVPRE)
#define OF_HEAD  (OF_FAV + N_FAV)
#define OF_MT    (OF_HEAD + N_HEAD)
#define OF_WT    (OF_MT + N_MT)
#define OF_WV    (OF_WT + N_WT)
#define SCRATCH_FLOATS (OF_WV + 1024)

__device__ float g_scratch[SCRATCH_FLOATS];

// ======================= helpers ===========================================
__device__ __forceinline__ uint32_t smem_u32(const void* p) {
    uint32_t a;
    asm("{ .reg .u64 t; cvta.to.shared.u64 t, %1; cvt.u32.u64 %0, t; }"
        : "=r"(a) : "l"(p));
    return a;
}
__device__ __forceinline__ uint32_t pk2(__nv_bfloat16 a, __nv_bfloat16 b) {
    __nv_bfloat162 t = __halves2bfloat162(a, b);
    return *reinterpret_cast<uint32_t*>(&t);
}
__device__ __forceinline__ uint32_t f2tf32(float x) {
    uint32_t u;
    asm("cvt.rna.tf32.f32 %0, %1;" : "=r"(u) : "f"(x));
    return u;
}

#define LDSM_X4(r0, r1, r2, r3, addr) \
    asm volatile("ldmatrix.sync.aligned.m8n8.x4.shared.b16 {%0,%1,%2,%3}, [%4];" \
                 : "=r"(r0), "=r"(r1), "=r"(r2), "=r"(r3) : "r"(addr))

#define MMA16816(d, a, b0, b1) \
    asm volatile("mma.sync.aligned.m16n8k16.row.col.f32.bf16.bf16.f32 " \
                 "{%0,%1,%2,%3}, {%4,%5,%6,%7}, {%8,%9}, {%0,%1,%2,%3};" \
                 : "+f"((d)[0]), "+f"((d)[1]), "+f"((d)[2]), "+f"((d)[3]) \
                 : "r"((a)[0]), "r"((a)[1]), "r"((a)[2]), "r"((a)[3]), \
                   "r"(b0), "r"(b1))

#define MMATF32(d, a, b0, b1) \
    asm volatile("mma.sync.aligned.m16n8k8.row.col.f32.tf32.tf32.f32 " \
                 "{%0,%1,%2,%3}, {%4,%5,%6,%7}, {%8,%9}, {%0,%1,%2,%3};" \
                 : "+f"((d)[0]), "+f"((d)[1]), "+f"((d)[2]), "+f"((d)[3]) \
                 : "r"((a)[0]), "r"((a)[1]), "r"((a)[2]), "r"((a)[3]), \
                   "r"(b0), "r"(b1))

// ===========================================================================
// (A) Split-bf16 3-pass NT GEMM (proven) — used for Mt only (full precision).
// ===========================================================================
#define AST 80
#define PL_AHI 0
#define PL_ALO 10240
#define PL_BHI 20480
#define PL_BLO 30720

__global__ __launch_bounds__(256)
void mma_gemm(const float* __restrict__ A, long long lda, long long zA,
              const float* __restrict__ Bt, long long ldb, long long zB,
              const float* __restrict__ bias, long long zBias,
              float* __restrict__ C, long long ldc, long long zC,
              int K, int relu)
{
    __shared__ __align__(16) char smem[40960];
    const uint32_t sb = smem_u32(smem);

    A  += (long long)blockIdx.z * zA;
    Bt += (long long)blockIdx.z * zB;
    C  += (long long)blockIdx.z * zC;
    if (bias) bias += (long long)blockIdx.z * zBias;

    const int tid = threadIdx.x;
    const int wid = tid >> 5, lid = tid & 31;
    const long long bm = (long long)blockIdx.y * 128;
    const long long bn = (long long)blockIdx.x * 128;
    const int wm = (wid & 1) * 64;
    const int wn = (wid >> 1) * 32;

    float acc[4][4][4];
#pragma unroll
    for (int mt = 0; mt < 4; mt++)
#pragma unroll
        for (int nt = 0; nt < 4; nt++)
#pragma unroll
            for (int r = 0; r < 4; r++) acc[mt][nt][r] = 0.0f;

    const int q = lid >> 3, qr = lid & 7;

    float4 pa[4], pb[4];
#pragma unroll
    for (int i = 0; i < 4; i++) {
        int idx = i * 256 + tid;
        int r = idx >> 3, c4 = idx & 7;
        pa[i] = *(const float4*)(A  + (bm + r) * lda + c4 * 4);
        pb[i] = *(const float4*)(Bt + (bn + r) * ldb + c4 * 4);
    }

    for (int k0 = 0; k0 < K; k0 += 32) {
#pragma unroll
        for (int i = 0; i < 4; i++) {
            int idx = i * 256 + tid;
            int r = idx >> 3, c4 = idx & 7;
            float4 v = pa[i];
            __nv_bfloat16 h0 = __float2bfloat16_rn(v.x);
            __nv_bfloat16 h1 = __float2bfloat16_rn(v.y);
            __nv_bfloat16 h2 = __float2bfloat16_rn(v.z);
            __nv_bfloat16 h3 = __float2bfloat16_rn(v.w);
            __nv_bfloat16 l0 = __float2bfloat16_rn(v.x - __bfloat162float(h0));
            __nv_bfloat16 l1 = __float2bfloat16_rn(v.y - __bfloat162float(h1));
            __nv_bfloat16 l2 = __float2bfloat16_rn(v.z - __bfloat162float(h2));
            __nv_bfloat16 l3 = __float2bfloat16_rn(v.w - __bfloat162float(h3));
            *(uint2*)(smem + PL_AHI + r * AST + c4 * 8) = make_uint2(pk2(h0, h1), pk2(h2, h3));
            *(uint2*)(smem + PL_ALO + r * AST + c4 * 8) = make_uint2(pk2(l0, l1), pk2(l2, l3));
            v = pb[i];
            h0 = __float2bfloat16_rn(v.x); h1 = __float2bfloat16_rn(v.y);
            h2 = __float2bfloat16_rn(v.z); h3 = __float2bfloat16_rn(v.w);
            l0 = __float2bfloat16_rn(v.x - __bfloat162float(h0));
            l1 = __float2bfloat16_rn(v.y - __bfloat162float(h1));
            l2 = __float2bfloat16_rn(v.z - __bfloat162float(h2));
            l3 = __float2bfloat16_rn(v.w - __bfloat162float(h3));
            *(uint2*)(smem + PL_BHI + r * AST + c4 * 8) = make_uint2(pk2(h0, h1), pk2(h2, h3));
            *(uint2*)(smem + PL_BLO + r * AST + c4 * 8) = make_uint2(pk2(l0, l1), pk2(l2, l3));
        }
        __syncthreads();

        if (k0 + 32 < K) {
#pragma unroll
            for (int i = 0; i < 4; i++) {
                int idx = i * 256 + tid;
                int r = idx >> 3, c4 = idx & 7;
                pa[i] = *(const float4*)(A  + (bm + r) * lda + k0 + 32 + c4 * 4);
                pb[i] = *(const float4*)(Bt + (bn + r) * ldb + k0 + 32 + c4 * 4);
            }
        }

#pragma unroll
        for (int kk = 0; kk < 32; kk += 16) {
            uint32_t ah[4][4], al[4][4], bh[2][4], bl[2][4];
#pragma unroll
            for (int mt = 0; mt < 4; mt++) {
                uint32_t row = wm + mt * 16 + (q & 1) * 8 + qr;
                uint32_t off = row * AST + kk * 2 + (q >> 1) * 16;
                LDSM_X4(ah[mt][0], ah[mt][1], ah[mt][2], ah[mt][3], sb + PL_AHI + off);
                LDSM_X4(al[mt][0], al[mt][1], al[mt][2], al[mt][3], sb + PL_ALO + off);
            }
#pragma unroll
            for (int nt2 = 0; nt2 < 2; nt2++) {
                uint32_t row = wn + nt2 * 16 + (q >> 1) * 8 + qr;
                uint32_t off = row * AST + kk * 2 + (q & 1) * 16;
                LDSM_X4(bh[nt2][0], bh[nt2][1], bh[nt2][2], bh[nt2][3], sb + PL_BHI + off);
                LDSM_X4(bl[nt2][0], bl[nt2][1], bl[nt2][2], bl[nt2][3], sb + PL_BLO + off);
            }
#pragma unroll
            for (int mt = 0; mt < 4; mt++) {
#pragma unroll
                for (int nt = 0; nt < 4; nt++) {
                    int n2 = nt >> 1, o = (nt & 1) * 2;
                    MMA16816(acc[mt][nt], ah[mt], bh[n2][o], bh[n2][o + 1]);
                    MMA16816(acc[mt][nt], ah[mt], bl[n2][o], bl[n2][o + 1]);
                    MMA16816(acc[mt][nt], al[mt], bh[n2][o], bh[n2][o + 1]);
                }
            }
        }
        __syncthreads();
    }

    const int mrow = lid >> 2, ncol = (lid & 3) * 2;
#pragma unroll
    for (int mt = 0; mt < 4; mt++) {
        long long r0 = bm + wm + mt * 16 + mrow;
        long long r1 = r0 + 8;
#pragma unroll
        for (int nt = 0; nt < 4; nt++) {
            long long col = bn + wn + nt * 8 + ncol;
            float b0 = 0.0f, b1 = 0.0f;
            if (bias) { b0 = bias[col]; b1 = bias[col + 1]; }
            float o0 = acc[mt][nt][0] + b0, o1 = acc[mt][nt][1] + b1;
            float o2 = acc[mt][nt][2] + b0, o3 = acc[mt][nt][3] + b1;
            if (relu) {
                o0 = fmaxf(o0, 0.0f); o1 = fmaxf(o1, 0.0f);
                o2 = fmaxf(o2, 0.0f); o3 = fmaxf(o3, 0.0f);
            }
            *(float2*)(C + r0 * ldc + col) = make_float2(o0, o1);
            *(float2*)(C + r1 * ldc + col) = make_float2(o2, o3);
        }
    }
}

// ===========================================================================
// (B) tf32 single-pass NT GEMM v2 — packed-pair smem layout, LDS.64 frags.
// Column c stored at packed pos p(c) = (c>>3)*8 + (c&3)*2 + ((c>>2)&1),
// so pairs (c, c+4) are adjacent. Row stride 40 floats (== 8 mod 32) ->
// conflict-free LDS.64 fragment loads; STS.128 sweeps all banks.
// ===========================================================================
#define TST 40

__global__ __launch_bounds__(256)
void tf32_gemm(const float* __restrict__ A, long long lda, long long zA,
               const float* __restrict__ Bt, long long ldb, long long zB,
               const float* __restrict__ bias, long long zBias,
               float* __restrict__ C, long long ldc, long long zC,
               int K, int relu)
{
    __shared__ __align__(16) float sA[128 * TST];
    __shared__ __align__(16) float sB[128 * TST];

    A  += (long long)blockIdx.z * zA;
    Bt += (long long)blockIdx.z * zB;
    C  += (long long)blockIdx.z * zC;
    if (bias) bias += (long long)blockIdx.z * zBias;

    const int tid = threadIdx.x;
    const int wid = tid >> 5, lid = tid & 31;
    const long long bm = (long long)blockIdx.y * 128;
    const long long bn = (long long)blockIdx.x * 128;
    const int wm = (wid & 1) * 64;
    const int wn = (wid >> 1) * 32;
    const int g = lid >> 2, tig = lid & 3;

    float acc[4][4][4];
#pragma unroll
    for (int mt = 0; mt < 4; mt++)
#pragma unroll
        for (int nt = 0; nt < 4; nt++)
#pragma unroll
            for (int r = 0; r < 4; r++) acc[mt][nt][r] = 0.0f;

    // load slots: 4 per thread; slot id = s*256+tid; row = id>>3, sub = id&7
    // sub -> j = sub>>1 (8-col group), i = sub&1; cols {8j+2i, 8j+2i+1, +4, +5}
    int rowv[4], coffv[4], poffv[4];
#pragma unroll
    for (int s = 0; s < 4; s++) {
        int id = s * 256 + tid;
        rowv[s] = id >> 3;
        int sub = id & 7;
        coffv[s] = (sub >> 1) * 8 + (sub & 1) * 2;
        poffv[s] = (sub >> 1) * 8 + (sub & 1) * 4;
    }

    float2 pa0[4], pa1[4], pb0[4], pb1[4];
#pragma unroll
    for (int s = 0; s < 4; s++) {
        pa0[s] = *(const float2*)(A  + (bm + rowv[s]) * lda + coffv[s]);
        pa1[s] = *(const float2*)(A  + (bm + rowv[s]) * lda + coffv[s] + 4);
        pb0[s] = *(const float2*)(Bt + (bn + rowv[s]) * ldb + coffv[s]);
        pb1[s] = *(const float2*)(Bt + (bn + rowv[s]) * ldb + coffv[s] + 4);
    }

    for (int k0 = 0; k0 < K; k0 += 32) {
        // store prefetched slab as tf32, packed-pair order {c, c+4, c+1, c+5}
#pragma unroll
        for (int s = 0; s < 4; s++) {
            uint4 t;
            t.x = f2tf32(pa0[s].x); t.y = f2tf32(pa1[s].x);
            t.z = f2tf32(pa0[s].y); t.w = f2tf32(pa1[s].y);
            *(uint4*)&sA[rowv[s] * TST + poffv[s]] = t;
            t.x = f2tf32(pb0[s].x); t.y = f2tf32(pb1[s].x);
            t.z = f2tf32(pb0[s].y); t.w = f2tf32(pb1[s].y);
            *(uint4*)&sB[rowv[s] * TST + poffv[s]] = t;
        }
        __syncthreads();

        if (k0 + 32 < K) {
#pragma unroll
            for (int s = 0; s < 4; s++) {
                pa0[s] = *(const float2*)(A  + (bm + rowv[s]) * lda + k0 + 32 + coffv[s]);
                pa1[s] = *(const float2*)(A  + (bm + rowv[s]) * lda + k0 + 32 + coffv[s] + 4);
                pb0[s] = *(const float2*)(Bt + (bn + rowv[s]) * ldb + k0 + 32 + coffv[s]);
                pb1[s] = *(const float2*)(Bt + (bn + rowv[s]) * ldb + k0 + 32 + coffv[s] + 4);
            }
        }

#pragma unroll
        for (int ks = 0; ks < 4; ks++) {
            uint32_t af[4][4], bf[4][2];
            const int cp = ks * 8 + tig * 2;     // packed offset of (cb, cb+4)
#pragma unroll
            for (int mt = 0; mt < 4; mt++) {
                int r0 = wm + mt * 16 + g;
                float2 lo = *(const float2*)&sA[r0 * TST + cp];        // (a0, a2)
                float2 hi = *(const float2*)&sA[(r0 + 8) * TST + cp];  // (a1, a3)
                af[mt][0] = __float_as_uint(lo.x);
                af[mt][1] = __float_as_uint(hi.x);
                af[mt][2] = __float_as_uint(lo.y);
                af[mt][3] = __float_as_uint(hi.y);
            }
#pragma unroll
            for (int nt = 0; nt < 4; nt++) {
                int n0 = wn + nt * 8 + g;
                float2 bb = *(const float2*)&sB[n0 * TST + cp];        // (b0, b1)
                bf[nt][0] = __float_as_uint(bb.x);
                bf[nt][1] = __float_as_uint(bb.y);
            }
#pragma unroll
            for (int mt = 0; mt < 4; mt++)
#pragma unroll
                for (int nt = 0; nt < 4; nt++)
                    MMATF32(acc[mt][nt], af[mt], bf[nt][0], bf[nt][1]);
        }
        __syncthreads();
    }

    const int mrow = lid >> 2, ncol = (lid & 3) * 2;
#pragma unroll
    for (int mt = 0; mt < 4; mt++) {
        long long r0 = bm + wm + mt * 16 + mrow;
        long long r1 = r0 + 8;
#pragma unroll
        for (int nt = 0; nt < 4; nt++) {
            long long col = bn + wn + nt * 8 + ncol;
            float b0 = 0.0f, b1 = 0.0f;
            if (bias) { b0 = bias[col]; b1 = bias[col + 1]; }
            float o0 = acc[mt][nt][0] + b0, o1 = acc[mt][nt][1] + b1;
            float o2 = acc[mt][nt][2] + b0, o3 = acc[mt][nt][3] + b1;
            if (relu) {
                o0 = fmaxf(o0, 0.0f); o1 = fmaxf(o1, 0.0f);
                o2 = fmaxf(o2, 0.0f); o3 = fmaxf(o3, 0.0f);
            }
            *(float2*)(C + r0 * ldc + col) = make_float2(o0, o1);
            *(float2*)(C + r1 * ldc + col) = make_float2(o2, o3);
        }
    }
}

// ---------------------------------------------------------------------------
// transpose 1024x1024 fp32 (z selects matrix): out[i,j] = in[j,i]
// ---------------------------------------------------------------------------
__global__ __launch_bounds__(256)
void tr1024(const float* __restrict__ in, float* __restrict__ out)
{
    __shared__ float t[32][33];
    in  += (size_t)blockIdx.z * DD * DD;
    out += (size_t)blockIdx.z * DD * DD;
    int x = blockIdx.x * 32 + threadIdx.x;
    int y = blockIdx.y * 32 + threadIdx.y;
#pragma unroll
    for (int i = 0; i < 4; i++)
        t[threadIdx.y + 8 * i][threadIdx.x] = in[(size_t)(y + 8 * i) * DD + x];
    __syncthreads();
    int x2 = blockIdx.y * 32 + threadIdx.x;
    int y2 = blockIdx.x * 32 + threadIdx.y;
#pragma unroll
    for (int i = 0; i < 4; i++)
        out[(size_t)(y2 + 8 * i) * DD + x2] = t[threadIdx.x][threadIdx.y + 8 * i];
}

// wv[k] = sum_e bq[e] * Wk[e,k]
__global__ void vec_kernel(const float* __restrict__ in_w,
                           const float* __restrict__ in_b,
                           float* __restrict__ wv)
{
    int k = blockIdx.x * 256 + threadIdx.x;
    const float* wkm = in_w + (size_t)DD * DD;
    const float* bq = in_b;
    float sv = 0.0f;
    for (int e = 0; e < DD; e++) sv += bq[e] * wkm[(size_t)e * DD + k];
    wv[k] = sv;
}

// ---------------------------------------------------------------------------
// attention: scores[s,t] = (t1[b,s].q[b,t] + gv[t]) / 32, softmax over t
// gv fused in-kernel (validated in R6).
// ---------------------------------------------------------------------------
__global__ __launch_bounds__(256)
void attn_kernel(const float* __restrict__ q, const float* __restrict__ t1,
                 const float* __restrict__ wv, float* __restrict__ attn)
{
    int b = blockIdx.x;
    __shared__ float sq[32 * 65];
    __shared__ float st[32 * 65];
    __shared__ float ssc[32 * 33];
    __shared__ float swv[64];
    __shared__ float gvp[8][33];
    const float* qb = q  + (size_t)b * SS * DD;
    const float* tbp = t1 + (size_t)b * SS * DD;
    int tid = threadIdx.x;
    int t = tid & 31, s0 = tid >> 5;
    float acc0 = 0, acc1 = 0, acc2 = 0, acc3 = 0, gvacc = 0;

    for (int kc = 0; kc < DD; kc += 64) {
        if (tid < 64) swv[tid] = wv[kc + tid];
        for (int i = tid; i < 32 * 16; i += 256) {
            int r = i >> 4, c4 = (i & 15) * 4;
            float4 a = *(const float4*)(qb + (size_t)r * DD + kc + c4);
            float4 v = *(const float4*)(tbp + (size_t)r * DD + kc + c4);
            sq[r * 65 + c4 + 0] = a.x; sq[r * 65 + c4 + 1] = a.y;
            sq[r * 65 + c4 + 2] = a.z; sq[r * 65 + c4 + 3] = a.w;
            st[r * 65 + c4 + 0] = v.x; st[r * 65 + c4 + 1] = v.y;
            st[r * 65 + c4 + 2] = v.z; st[r * 65 + c4 + 3] = v.w;
        }
        __syncthreads();
#pragma unroll 8
        for (int kk = 0; kk < 64; kk++) {
            float rq = sq[t * 65 + kk];
            acc0 += st[(s0 +  0) * 65 + kk] * rq;
            acc1 += st[(s0 +  8) * 65 + kk] * rq;
            acc2 += st[(s0 + 16) * 65 + kk] * rq;
            acc3 += st[(s0 + 24) * 65 + kk] * rq;
        }
#pragma unroll
        for (int j = 0; j < 8; j++)
            gvacc += sq[t * 65 + s0 * 8 + j] * swv[s0 * 8 + j];
        __syncthreads();
    }
    gvp[s0][t] = gvacc;
    __syncthreads();
    if (s0 == 0) {
        float s = 0.0f;
#pragma unroll
        for (int j = 0; j < 8; j++) s += gvp[j][t];
        gvp[0][t] = s;
    }
    __syncthreads();
    float vv = gvp[0][t];
    const float sc = 1.0f / 32.0f;
    ssc[(s0 +  0) * 33 + t] = (acc0 + vv) * sc;
    ssc[(s0 +  8) * 33 + t] = (acc1 + vv) * sc;
    ssc[(s0 + 16) * 33 + t] = (acc2 + vv) * sc;
    ssc[(s0 + 24) * 33 + t] = (acc3 + vv) * sc;
    __syncthreads();
    if (tid < 32) {
        float mx = -1e30f;
        for (int j = 0; j < 32; j++) mx = fmaxf(mx, ssc[tid * 33 + j]);
        float sum = 0.0f;
        for (int j = 0; j < 32; j++) {
            float e = expf(ssc[tid * 33 + j] - mx);
            ssc[tid * 33 + j] = e; sum += e;
        }
        float inv = 1.0f / sum;
        for (int j = 0; j < 32; j++)
            attn[(size_t)b * SS * SS + tid * 32 + j] = ssc[tid * 33 + j] * inv;
    }
}

// ---------------------------------------------------------------------------
// classifier scalar + softmax halves -> d_a/d_v (out tail + scratch)
// ---------------------------------------------------------------------------
__global__ __launch_bounds__(512)
void cls_head_kernel(const float* __restrict__ h, const float* __restrict__ w2,
                     const float* __restrict__ b2, float* __restrict__ dav,
                     float* __restrict__ out_d)
{
    int b = blockIdx.x;
    __shared__ float sd[32];
    int w = threadIdx.x >> 5, lane = threadIdx.x & 31;
    for (int s = w; s < SS; s += 16) {
        const float* hr = h + ((size_t)b * SS + s) * HH;
        const float* wr = w2 + (size_t)s * HH;
        float acc = 0.0f;
        for (int k = lane; k < HH; k += 32) acc += hr[k] * wr[k];
#pragma unroll
        for (int o = 16; o; o >>= 1) acc += __shfl_down_sync(0xffffffffu, acc, o);
        if (lane == 0) sd[s] = fmaxf(acc + b2[s], 0.0f);
    }
    __syncthreads();
    if (threadIdx.x < 2) {
        int off = threadIdx.x * PP;
        float mx = -1e30f;
        for (int j = 0; j < PP; j++) mx = fmaxf(mx, sd[off + j]);
        float sum = 0.0f;
        float e[PP];
        for (int j = 0; j < PP; j++) { e[j] = expf(sd[off + j] - mx); sum += e[j]; }
        float inv = 1.0f / sum;
        float* outp = out_d + (size_t)threadIdx.x * BB * PP + (size_t)b * PP;
        for (int j = 0; j < PP; j++) {
            float val = e[j] * inv;
            dav[b * SS + off + j] = val;
            outp[j] = val;
        }
    }
}

// ---------------------------------------------------------------------------
// mix in q-space: wa[t]=sum_s d_a[s]attn[s,t]; avmix_a[b]=sum_t wa[t] q[b,t,:]
// ---------------------------------------------------------------------------
__global__ __launch_bounds__(128)
void combine_kernel(const float* __restrict__ attn, const float* __restrict__ q,
                    const float* __restrict__ dav, float* __restrict__ avmix)
{
    int b = blockIdx.x;
    __shared__ float sat[SS * SS];
    __shared__ float wa[SS], wvv[SS];
    int tid = threadIdx.x;
    for (int i = tid; i < SS * SS; i += 128) sat[i] = attn[(size_t)b * SS * SS + i];
    __syncthreads();
    if (tid < SS) {
        float a = 0.0f, v = 0.0f;
        for (int s = 0; s < PP; s++) {
            a += dav[b * SS + s]      * sat[s * SS + tid];
            v += dav[b * SS + PP + s] * sat[(PP + s) * SS + tid];
        }
        wa[tid] = a; wvv[tid] = v;
    }
    __syncthreads();
    const float* qb = q + (size_t)b * SS * DD;
    for (int d = tid; d < DD; d += 128) {
        float a = 0.0f, v = 0.0f;
#pragma unroll
        for (int t = 0; t < SS; t++) {
            float x = qb[(size_t)t * DD + d];
            a += wa[t] * x;
            v += wvv[t] * x;
        }
        avmix[(size_t)b * DD + d] = a;
        avmix[((size_t)BB + b) * DD + d] = v;
    }
}

// fusion = 0.5*(audio+video)
__global__ void avg_kernel(float* __restrict__ fav)
{
    size_t i = (size_t)blockIdx.x * 256 + threadIdx.x;
    fav[i] = 0.5f * (fav[(size_t)BB * DD + i] + fav[(size_t)2 * BB * DD + i]);
}

// ---------------------------------------------------------------------------
// LayerNorm(512) + ReLU per row
// ---------------------------------------------------------------------------
__global__ __launch_bounds__(128)
void ln_kernel(const float* __restrict__ x, const float* __restrict__ g,
               const float* __restrict__ be, float* __restrict__ out)
{
    int row = blockIdx.x;
    const float* xr = x + (size_t)row * FF;
    int tid = threadIdx.x;
    __shared__ float sm[4];
    float v[4];
    float s = 0.0f;
#pragma unroll
    for (int i = 0; i < 4; i++) { v[i] = xr[tid + 128 * i]; s += v[i]; }
#pragma unroll
    for (int o = 16; o; o >>= 1) s += __shfl_down_sync(0xffffffffu, s, o);
    if ((tid & 31) == 0) sm[tid >> 5] = s;
    __syncthreads();
    float mu = (sm[0] + sm[1] + sm[2] + sm[3]) * (1.0f / FF);
    __syncthreads();
    float qv = 0.0f;
#pragma unroll
    for (int i = 0; i < 4; i++) { float d = v[i] - mu; qv += d * d; }
#pragma unroll
    for (int o = 16; o; o >>= 1) qv += __shfl_down_sync(0xffffffffu, qv, o);
    if ((tid & 31) == 0) sm[tid >> 5] = qv;
    __syncthreads();
    float var = (sm[0] + sm[1] + sm[2] + sm[3]) * (1.0f / FF);
    float rstd = rsqrtf(var + 1e-5f);
    float* orow = out + (size_t)row * FF;
#pragma unroll
    for (int i = 0; i < 4; i++) {
        int c = tid + 128 * i;
        float y = (v[i] - mu) * rstd * g[c] + be[c];
        orow[c] = fmaxf(y, 0.0f);
    }
}

// ---------------------------------------------------------------------------
extern "C" void kernel_launch(void* const* d_in, const int* in_sizes, int n_in,
                              void* d_out, int out_size)
{
    const float* q      = (const float*)d_in[0];
    const float* in_w   = (const float*)d_in[1];
    const float* in_b   = (const float*)d_in[2];
    const float* out_w  = (const float*)d_in[3];
    const float* out_b  = (const float*)d_in[4];
    const float* cls_w1 = (const float*)d_in[5];
    const float* cls_b1 = (const float*)d_in[6];
    const float* cls_w2 = (const float*)d_in[7];
    const float* cls_b2 = (const float*)d_in[8];
    const float* fus_w  = (const float*)d_in[9];
    const float* fus_b  = (const float*)d_in[10];
    const float* fus_g  = (const float*)d_in[11];
    const float* fus_be = (const float*)d_in[12];
    const float* pa_w   = (const float*)d_in[13];
    const float* pa_b   = (const float*)d_in[14];
    const float* pa_g   = (const float*)d_in[15];
    const float* pa_be  = (const float*)d_in[16];
    const float* pv_w   = (const float*)d_in[17];
    const float* pv_b   = (const float*)d_in[18];
    const float* pv_g   = (const float*)d_in[19];
    const float* pv_be  = (const float*)d_in[20];
    float* out = (float*)d_out;

    float* sp = nullptr;
    cudaGetSymbolAddress((void**)&sp, g_scratch);

    float* t1    = sp + OF_T1;
    float* h     = sp + OF_H;
    float* attn  = sp + OF_ATTN;
    float* dav   = sp + OF_DAV;
    float* avmix = sp + OF_AVMIX;
    float* avpre = sp + OF_AVPRE;
    float* fav   = sp + OF_FAV;
    float* headb = sp + OF_HEAD;
    float* Mt    = sp + OF_MT;
    float* WqT   = sp + OF_WT;
    float* WkT   = sp + OF_WT + (size_t)DD * DD;
    float* wv    = sp + OF_WV;

    const float* wv_w = in_w + (size_t)2 * DD * DD;
    const float* bv = in_b + 2 * DD;

    // 1. WqT, WkT transposes
    tr1024<<<dim3(32, 32, 2), dim3(32, 8)>>>(in_w, WqT);
    // 2. bias fold
    vec_kernel<<<4, 256>>>(in_w, in_b, wv);
    // 3. Mt[n,k] = sum_e WkT[n,e]*WqT[k,e]   (bf16 3-pass, full precision)
    mma_gemm<<<dim3(8, 8, 1), 256>>>(WkT, DD, 0, WqT, DD, 0, nullptr, 0,
                                     Mt, DD, 0, DD, 0);
    // 4. t1 = q @ M   (tf32)
    tf32_gemm<<<dim3(8, 512, 1), 256>>>(q, DD, 0, Mt, DD, 0, nullptr, 0,
                                        t1, DD, 0, DD, 0);
    // 5. h = relu(q @ W1[s]^T + b1[s])   (tf32)
    tf32_gemm<<<dim3(4, 16, 32), 256>>>(q, SS * DD, DD,
                                        cls_w1, DD, (long long)HH * DD,
                                        cls_b1, HH, h, SS * HH, HH, DD, 1);
    // 6. attention softmax (fused gv)
    attn_kernel<<<BB, 256>>>(q, t1, wv, attn);
    // 7. classifier head -> dav + out tail
    cls_head_kernel<<<BB, 512>>>(h, cls_w2, cls_b2, dav, out + (size_t)3 * BB * FF);
    // 8. q-space mix
    combine_kernel<<<BB, 128>>>(attn, q, dav, avmix);
    // 9. avpre = avmix @ Wv^T + bv   (tf32)
    tf32_gemm<<<dim3(8, 32, 1), 256>>>(avmix, DD, 0, wv_w, DD, 0, bv, 0,
                                       avpre, DD, 0, DD, 0);
    // 10. audio/video = avpre @ out_w^T + out_b -> fav[B..3B)   (tf32)
    tf32_gemm<<<dim3(8, 32, 1), 256>>>(avpre, DD, 0, out_w, DD, 0, out_b, 0,
                                       fav + (size_t)BB * DD, DD, 0, DD, 0);
    // 11. fusion
    avg_kernel<<<(BB * DD) / 256, 256>>>(fav);
    // 12-14. projector heads   (tf32)
    tf32_gemm<<<dim3(4, 16, 1), 256>>>(fav, DD, 0, fus_w, DD, 0, fus_b, 0,
                                       headb, FF, 0, DD, 0);
    tf32_gemm<<<dim3(4, 16, 1), 256>>>(fav + (size_t)BB * DD, DD, 0, pa_w, DD, 0,
                                       pa_b, 0, headb + (size_t)BB * FF, FF, 0, DD, 0);
    tf32_gemm<<<dim3(4, 16, 1), 256>>>(fav + (size_t)2 * BB * DD, DD, 0, pv_w, DD, 0,
                                       pv_b, 0, headb + (size_t)2 * BB * FF, FF, 0, DD, 0);
    // 15-17. LayerNorm + ReLU
    ln_kernel<<<BB, 128>>>(headb, fus_g, fus_be, out);
    ln_kernel<<<BB, 128>>>(headb + (size_t)BB * FF, pa_g, pa_be, out + (size_t)BB * FF);
    ln_kernel<<<BB, 128>>>(headb + (size_t)2 * BB * FF, pv_g, pv_be, out + (size_t)2 * BB * FF);
}

// round 12
// speedup vs baseline: 1.0591x; 1.0591x over previous
#include <cuda_runtime.h>
#include <cuda_bf16.h>
#include <stdint.h>
#include <math.h>

// Problem dims
#define BB 2048
#define SS 32
#define DD 1024
#define PP 16
#define FF 512
#define HH 512

// ---------------- scratch layout (single __device__ array) ------------------
#define N_T1    ((size_t)BB * SS * DD)
#define N_H     ((size_t)BB * SS * HH)
#define N_ATTN  ((size_t)BB * SS * SS)
#define N_DAV   ((size_t)BB * SS)
#define N_AVMIX ((size_t)2 * BB * DD)
#define N_AVPRE ((size_t)2 * BB * DD)
#define N_FAV   ((size_t)3 * BB * DD)
#define N_HEAD  ((size_t)3 * BB * FF)
#define N_MT    ((size_t)DD * DD)
#define N_WT    ((size_t)2 * DD * DD)

#define OF_T1    ((size_t)0)
#define OF_H     (OF_T1 + N_T1)
#define OF_ATTN  (OF_H + N_H)
#define OF_DAV   (OF_ATTN + N_ATTN)
#define OF_AVMIX (OF_DAV + N_DAV)
#define OF_AVPRE (OF_AVMIX + N_AVMIX)
#define OF_FAV   (OF_AVPRE + N_AVPRE)
#define OF_HEAD  (OF_FAV + N_FAV)
#define OF_MT    (OF_HEAD + N_HEAD)
#define OF_WT    (OF_MT + N_MT)
#define OF_WV    (OF_WT + N_WT)
#define SCRATCH_FLOATS (OF_WV + 1024)

__device__ float g_scratch[SCRATCH_FLOATS];

// ======================= helpers ===========================================
__device__ __forceinline__ uint32_t smem_u32(const void* p) {
    uint32_t a;
    asm("{ .reg .u64 t; cvta.to.shared.u64 t, %1; cvt.u32.u64 %0, t; }"
        : "=r"(a) : "l"(p));
    return a;
}
__device__ __forceinline__ uint32_t pk2(__nv_bfloat16 a, __nv_bfloat16 b) {
    __nv_bfloat162 t = __halves2bfloat162(a, b);
    return *reinterpret_cast<uint32_t*>(&t);
}
__device__ __forceinline__ uint32_t f2tf32(float x) {
    uint32_t u;
    asm("cvt.rna.tf32.f32 %0, %1;" : "=r"(u) : "f"(x));
    return u;
}

#define LDSM_X4(r0, r1, r2, r3, addr) \
    asm volatile("ldmatrix.sync.aligned.m8n8.x4.shared.b16 {%0,%1,%2,%3}, [%4];" \
                 : "=r"(r0), "=r"(r1), "=r"(r2), "=r"(r3) : "r"(addr))

#define MMA16816(d, a, b0, b1) \
    asm volatile("mma.sync.aligned.m16n8k16.row.col.f32.bf16.bf16.f32 " \
                 "{%0,%1,%2,%3}, {%4,%5,%6,%7}, {%8,%9}, {%0,%1,%2,%3};" \
                 : "+f"((d)[0]), "+f"((d)[1]), "+f"((d)[2]), "+f"((d)[3]) \
                 : "r"((a)[0]), "r"((a)[1]), "r"((a)[2]), "r"((a)[3]), \
                   "r"(b0), "r"(b1))

#define MMATF32(d, a, b0, b1) \
    asm volatile("mma.sync.aligned.m16n8k8.row.col.f32.tf32.tf32.f32 " \
                 "{%0,%1,%2,%3}, {%4,%5,%6,%7}, {%8,%9}, {%0,%1,%2,%3};" \
                 : "+f"((d)[0]), "+f"((d)[1]), "+f"((d)[2]), "+f"((d)[3]) \
                 : "r"((a)[0]), "r"((a)[1]), "r"((a)[2]), "r"((a)[3]), \
                   "r"(b0), "r"(b1))

// ===========================================================================
// (A) Split-bf16 3-pass NT GEMM (proven R4 kernel) — small GEMMs, err ~1e-5.
// ===========================================================================
#define AST 80
#define PL_AHI 0
#define PL_ALO 10240
#define PL_BHI 20480
#define PL_BLO 30720

__global__ __launch_bounds__(256)
void mma_gemm(const float* __restrict__ A, long long lda, long long zA,
              const float* __restrict__ Bt, long long ldb, long long zB,
              const float* __restrict__ bias, long long zBias,
              float* __restrict__ C, long long ldc, long long zC,
              int K, int relu)
{
    __shared__ __align__(16) char smem[40960];
    const uint32_t sb = smem_u32(smem);

    A  += (long long)blockIdx.z * zA;
    Bt += (long long)blockIdx.z * zB;
    C  += (long long)blockIdx.z * zC;
    if (bias) bias += (long long)blockIdx.z * zBias;

    const int tid = threadIdx.x;
    const int wid = tid >> 5, lid = tid & 31;
    const long long bm = (long long)blockIdx.y * 128;
    const long long bn = (long long)blockIdx.x * 128;
    const int wm = (wid & 1) * 64;
    const int wn = (wid >> 1) * 32;

    float acc[4][4][4];
#pragma unroll
    for (int mt = 0; mt < 4; mt++)
#pragma unroll
        for (int nt = 0; nt < 4; nt++)
#pragma unroll
            for (int r = 0; r < 4; r++) acc[mt][nt][r] = 0.0f;

    const int q = lid >> 3, qr = lid & 7;

    float4 pa[4], pb[4];
#pragma unroll
    for (int i = 0; i < 4; i++) {
        int idx = i * 256 + tid;
        int r = idx >> 3, c4 = idx & 7;
        pa[i] = *(const float4*)(A  + (bm + r) * lda + c4 * 4);
        pb[i] = *(const float4*)(Bt + (bn + r) * ldb + c4 * 4);
    }

    for (int k0 = 0; k0 < K; k0 += 32) {
#pragma unroll
        for (int i = 0; i < 4; i++) {
            int idx = i * 256 + tid;
            int r = idx >> 3, c4 = idx & 7;
            float4 v = pa[i];
            __nv_bfloat16 h0 = __float2bfloat16_rn(v.x);
            __nv_bfloat16 h1 = __float2bfloat16_rn(v.y);
            __nv_bfloat16 h2 = __float2bfloat16_rn(v.z);
            __nv_bfloat16 h3 = __float2bfloat16_rn(v.w);
            __nv_bfloat16 l0 = __float2bfloat16_rn(v.x - __bfloat162float(h0));
            __nv_bfloat16 l1 = __float2bfloat16_rn(v.y - __bfloat162float(h1));
            __nv_bfloat16 l2 = __float2bfloat16_rn(v.z - __bfloat162float(h2));
            __nv_bfloat16 l3 = __float2bfloat16_rn(v.w - __bfloat162float(h3));
            *(uint2*)(smem + PL_AHI + r * AST + c4 * 8) = make_uint2(pk2(h0, h1), pk2(h2, h3));
            *(uint2*)(smem + PL_ALO + r * AST + c4 * 8) = make_uint2(pk2(l0, l1), pk2(l2, l3));
            v = pb[i];
            h0 = __float2bfloat16_rn(v.x); h1 = __float2bfloat16_rn(v.y);
            h2 = __float2bfloat16_rn(v.z); h3 = __float2bfloat16_rn(v.w);
            l0 = __float2bfloat16_rn(v.x - __bfloat162float(h0));
            l1 = __float2bfloat16_rn(v.y - __bfloat162float(h1));
            l2 = __float2bfloat16_rn(v.z - __bfloat162float(h2));
            l3 = __float2bfloat16_rn(v.w - __bfloat162float(h3));
            *(uint2*)(smem + PL_BHI + r * AST + c4 * 8) = make_uint2(pk2(h0, h1), pk2(h2, h3));
            *(uint2*)(smem + PL_BLO + r * AST + c4 * 8) = make_uint2(pk2(l0, l1), pk2(l2, l3));
        }
        __syncthreads();

        if (k0 + 32 < K) {
#pragma unroll
            for (int i = 0; i < 4; i++) {
                int idx = i * 256 + tid;
                int r = idx >> 3, c4 = idx & 7;
                pa[i] = *(const float4*)(A  + (bm + r) * lda + k0 + 32 + c4 * 4);
                pb[i] = *(const float4*)(Bt + (bn + r) * ldb + k0 + 32 + c4 * 4);
            }
        }

#pragma unroll
        for (int kk = 0; kk < 32; kk += 16) {
            uint32_t ah[4][4], al[4][4], bh[2][4], bl[2][4];
#pragma unroll
            for (int mt = 0; mt < 4; mt++) {
                uint32_t row = wm + mt * 16 + (q & 1) * 8 + qr;
                uint32_t off = row * AST + kk * 2 + (q >> 1) * 16;
                LDSM_X4(ah[mt][0], ah[mt][1], ah[mt][2], ah[mt][3], sb + PL_AHI + off);
                LDSM_X4(al[mt][0], al[mt][1], al[mt][2], al[mt][3], sb + PL_ALO + off);
            }
#pragma unroll
            for (int nt2 = 0; nt2 < 2; nt2++) {
                uint32_t row = wn + nt2 * 16 + (q >> 1) * 8 + qr;
                uint32_t off = row * AST + kk * 2 + (q & 1) * 16;
                LDSM_X4(bh[nt2][0], bh[nt2][1], bh[nt2][2], bh[nt2][3], sb + PL_BHI + off);
                LDSM_X4(bl[nt2][0], bl[nt2][1], bl[nt2][2], bl[nt2][3], sb + PL_BLO + off);
            }
#pragma unroll
            for (int mt = 0; mt < 4; mt++) {
#pragma unroll
                for (int nt = 0; nt < 4; nt++) {
                    int n2 = nt >> 1, o = (nt & 1) * 2;
                    MMA16816(acc[mt][nt], ah[mt], bh[n2][o], bh[n2][o + 1]);
                    MMA16816(acc[mt][nt], ah[mt], bl[n2][o], bl[n2][o + 1]);
                    MMA16816(acc[mt][nt], al[mt], bh[n2][o], bh[n2][o + 1]);
                }
            }
        }
        __syncthreads();
    }

    const int mrow = lid >> 2, ncol = (lid & 3) * 2;
#pragma unroll
    for (int mt = 0; mt < 4; mt++) {
        long long r0 = bm + wm + mt * 16 + mrow;
        long long r1 = r0 + 8;
#pragma unroll
        for (int nt = 0; nt < 4; nt++) {
            long long col = bn + wn + nt * 8 + ncol;
            float b0 = 0.0f, b1 = 0.0f;
            if (bias) { b0 = bias[col]; b1 = bias[col + 1]; }
            float o0 = acc[mt][nt][0] + b0, o1 = acc[mt][nt][1] + b1;
            float o2 = acc[mt][nt][2] + b0, o3 = acc[mt][nt][3] + b1;
            if (relu) {
                o0 = fmaxf(o0, 0.0f); o1 = fmaxf(o1, 0.0f);
                o2 = fmaxf(o2, 0.0f); o3 = fmaxf(o3, 0.0f);
            }
            *(float2*)(C + r0 * ldc + col) = make_float2(o0, o1);
            *(float2*)(C + r1 * ldc + col) = make_float2(o2, o3);
        }
    }
}

// ===========================================================================
// (B) tf32 single-pass NT GEMM v3 — ldmatrix fragment loads (tf32-as-b16).
// Row stride 36 floats (144 B) -> 8 distinct 16B phases per LDSM matrix.
// Per k-step: 4 A-LDSM.x4 + 2 B-LDSM.x4 + 16 MMA (was 24 scalar LDS).
// ===========================================================================
#define TST 36

__global__ __launch_bounds__(256)
void tf32_gemm(const float* __restrict__ A, long long lda, long long zA,
               const float* __restrict__ Bt, long long ldb, long long zB,
               const float* __restrict__ bias, long long zBias,
               float* __restrict__ C, long long ldc, long long zC,
               int K, int relu)
{
    __shared__ __align__(16) float sA[128 * TST];
    __shared__ __align__(16) float sB[128 * TST];

    A  += (long long)blockIdx.z * zA;
    Bt += (long long)blockIdx.z * zB;
    C  += (long long)blockIdx.z * zC;
    if (bias) bias += (long long)blockIdx.z * zBias;

    const int tid = threadIdx.x;
    const int wid = tid >> 5, lid = tid & 31;
    const long long bm = (long long)blockIdx.y * 128;
    const long long bn = (long long)blockIdx.x * 128;
    const int wm = (wid & 1) * 64;
    const int wn = (wid >> 1) * 32;

    float acc[4][4][4];
#pragma unroll
    for (int mt = 0; mt < 4; mt++)
#pragma unroll
        for (int nt = 0; nt < 4; nt++)
#pragma unroll
            for (int r = 0; r < 4; r++) acc[mt][nt][r] = 0.0f;

    // ldmatrix lane geometry: qm = lid>>3 selects matrix, jj = lid&7 row
    const int qm = lid >> 3, jj = lid & 7;
    // A x4 blocks: row += (qm&1)*8, col += (qm>>1)*4
    const uint32_t aBase = smem_u32(sA)
        + ((uint32_t)((wm + jj + (qm & 1) * 8) * TST + (qm >> 1) * 4)) * 4u;
    // B x4 blocks: row += (qm>>1)*8 (nt pair), col += (qm&1)*4
    const uint32_t bBase = smem_u32(sB)
        + ((uint32_t)((wn + jj + (qm >> 1) * 8) * TST + (qm & 1) * 4)) * 4u;

    float4 pa[4], pb[4];
#pragma unroll
    for (int i = 0; i < 4; i++) {
        int idx = i * 256 + tid;
        int r = idx >> 3, c4 = idx & 7;
        pa[i] = *(const float4*)(A  + (bm + r) * lda + c4 * 4);
        pb[i] = *(const float4*)(Bt + (bn + r) * ldb + c4 * 4);
    }

    for (int k0 = 0; k0 < K; k0 += 32) {
        // store prefetched slab as tf32 (plain column order)
#pragma unroll
        for (int i = 0; i < 4; i++) {
            int idx = i * 256 + tid;
            int r = idx >> 3, c4 = (idx & 7) * 4;
            float4 v = pa[i];
            uint4 t;
            t.x = f2tf32(v.x); t.y = f2tf32(v.y); t.z = f2tf32(v.z); t.w = f2tf32(v.w);
            *(uint4*)&sA[r * TST + c4] = t;
            v = pb[i];
            t.x = f2tf32(v.x); t.y = f2tf32(v.y); t.z = f2tf32(v.z); t.w = f2tf32(v.w);
            *(uint4*)&sB[r * TST + c4] = t;
        }
        __syncthreads();

        if (k0 + 32 < K) {
#pragma unroll
            for (int i = 0; i < 4; i++) {
                int idx = i * 256 + tid;
                int r = idx >> 3, c4 = idx & 7;
                pa[i] = *(const float4*)(A  + (bm + r) * lda + k0 + 32 + c4 * 4);
                pb[i] = *(const float4*)(Bt + (bn + r) * ldb + k0 + 32 + c4 * 4);
            }
        }

#pragma unroll
        for (int ks = 0; ks < 4; ks++) {
            uint32_t af[4][4], bf[4][2];
            const uint32_t co = (uint32_t)(ks * 8) * 4u;   // k-column byte offset
#pragma unroll
            for (int mt = 0; mt < 4; mt++) {
                LDSM_X4(af[mt][0], af[mt][1], af[mt][2], af[mt][3],
                        aBase + (uint32_t)(mt * 16 * TST) * 4u + co);
            }
#pragma unroll
            for (int np = 0; np < 2; np++) {
                LDSM_X4(bf[np * 2][0], bf[np * 2][1], bf[np * 2 + 1][0], bf[np * 2 + 1][1],
                        bBase + (uint32_t)(np * 16 * TST) * 4u + co);
            }
#pragma unroll
            for (int mt = 0; mt < 4; mt++)
#pragma unroll
                for (int nt = 0; nt < 4; nt++)
                    MMATF32(acc[mt][nt], af[mt], bf[nt][0], bf[nt][1]);
        }
        __syncthreads();
    }

    const int mrow = lid >> 2, ncol = (lid & 3) * 2;
#pragma unroll
    for (int mt = 0; mt < 4; mt++) {
        long long r0 = bm + wm + mt * 16 + mrow;
        long long r1 = r0 + 8;
#pragma unroll
        for (int nt = 0; nt < 4; nt++) {
            long long col = bn + wn + nt * 8 + ncol;
            float b0 = 0.0f, b1 = 0.0f;
            if (bias) { b0 = bias[col]; b1 = bias[col + 1]; }
            float o0 = acc[mt][nt][0] + b0, o1 = acc[mt][nt][1] + b1;
            float o2 = acc[mt][nt][2] + b0, o3 = acc[mt][nt][3] + b1;
            if (relu) {
                o0 = fmaxf(o0, 0.0f); o1 = fmaxf(o1, 0.0f);
                o2 = fmaxf(o2, 0.0f); o3 = fmaxf(o3, 0.0f);
            }
            *(float2*)(C + r0 * ldc + col) = make_float2(o0, o1);
            *(float2*)(C + r1 * ldc + col) = make_float2(o2, o3);
        }
    }
}

// ---------------------------------------------------------------------------
// transpose 1024x1024 fp32 (z selects matrix): out[i,j] = in[j,i]
// ---------------------------------------------------------------------------
__global__ __launch_bounds__(256)
void tr1024(const float* __restrict__ in, float* __restrict__ out)
{
    __shared__ float t[32][33];
    in  += (size_t)blockIdx.z * DD * DD;
    out += (size_t)blockIdx.z * DD * DD;
    int x = blockIdx.x * 32 + threadIdx.x;
    int y = blockIdx.y * 32 + threadIdx.y;
#pragma unroll
    for (int i = 0; i < 4; i++)
        t[threadIdx.y + 8 * i][threadIdx.x] = in[(size_t)(y + 8 * i) * DD + x];
    __syncthreads();
    int x2 = blockIdx.y * 32 + threadIdx.x;
    int y2 = blockIdx.x * 32 + threadIdx.y;
#pragma unroll
    for (int i = 0; i < 4; i++)
        out[(size_t)(y2 + 8 * i) * DD + x2] = t[threadIdx.x][threadIdx.y + 8 * i];
}

// wv[k] = sum_e bq[e] * Wk[e,k]
__global__ void vec_kernel(const float* __restrict__ in_w,
                           const float* __restrict__ in_b,
                           float* __restrict__ wv)
{
    int k = blockIdx.x * 256 + threadIdx.x;
    const float* wkm = in_w + (size_t)DD * DD;
    const float* bq = in_b;
    float sv = 0.0f;
    for (int e = 0; e < DD; e++) sv += bq[e] * wkm[(size_t)e * DD + k];
    wv[k] = sv;
}

// ---------------------------------------------------------------------------
// attention: scores[s,t] = (t1[b,s].q[b,t] + gv[t]) / 32, softmax over t
// gv fused in-kernel (validated R6/R7).
// ---------------------------------------------------------------------------
__global__ __launch_bounds__(256)
void attn_kernel(const float* __restrict__ q, const float* __restrict__ t1,
                 const float* __restrict__ wv, float* __restrict__ attn)
{
    int b = blockIdx.x;
    __shared__ float sq[32 * 65];
    __shared__ float st[32 * 65];
    __shared__ float ssc[32 * 33];
    __shared__ float swv[64];
    __shared__ float gvp[8][33];
    const float* qb = q  + (size_t)b * SS * DD;
    const float* tbp = t1 + (size_t)b * SS * DD;
    int tid = threadIdx.x;
    int t = tid & 31, s0 = tid >> 5;
    float acc0 = 0, acc1 = 0, acc2 = 0, acc3 = 0, gvacc = 0;

    for (int kc = 0; kc < DD; kc += 64) {
        if (tid < 64) swv[tid] = wv[kc + tid];
        for (int i = tid; i < 32 * 16; i += 256) {
            int r = i >> 4, c4 = (i & 15) * 4;
            float4 a = *(const float4*)(qb + (size_t)r * DD + kc + c4);
            float4 v = *(const float4*)(tbp + (size_t)r * DD + kc + c4);
            sq[r * 65 + c4 + 0] = a.x; sq[r * 65 + c4 + 1] = a.y;
            sq[r * 65 + c4 + 2] = a.z; sq[r * 65 + c4 + 3] = a.w;
            st[r * 65 + c4 + 0] = v.x; st[r * 65 + c4 + 1] = v.y;
            st[r * 65 + c4 + 2] = v.z; st[r * 65 + c4 + 3] = v.w;
        }
        __syncthreads();
#pragma unroll 8
        for (int kk = 0; kk < 64; kk++) {
            float rq = sq[t * 65 + kk];
            acc0 += st[(s0 +  0) * 65 + kk] * rq;
            acc1 += st[(s0 +  8) * 65 + kk] * rq;
            acc2 += st[(s0 + 16) * 65 + kk] * rq;
            acc3 += st[(s0 + 24) * 65 + kk] * rq;
        }
#pragma unroll
        for (int j = 0; j < 8; j++)
            gvacc += sq[t * 65 + s0 * 8 + j] * swv[s0 * 8 + j];
        __syncthreads();
    }
    gvp[s0][t] = gvacc;
    __syncthreads();
    if (s0 == 0) {
        float s = 0.0f;
#pragma unroll
        for (int j = 0; j < 8; j++) s += gvp[j][t];
        gvp[0][t] = s;
    }
    __syncthreads();
    float vv = gvp[0][t];
    const float sc = 1.0f / 32.0f;
    ssc[(s0 +  0) * 33 + t] = (acc0 + vv) * sc;
    ssc[(s0 +  8) * 33 + t] = (acc1 + vv) * sc;
    ssc[(s0 + 16) * 33 + t] = (acc2 + vv) * sc;
    ssc[(s0 + 24) * 33 + t] = (acc3 + vv) * sc;
    __syncthreads();
    if (tid < 32) {
        float mx = -1e30f;
        for (int j = 0; j < 32; j++) mx = fmaxf(mx, ssc[tid * 33 + j]);
        float sum = 0.0f;
        for (int j = 0; j < 32; j++) {
            float e = expf(ssc[tid * 33 + j] - mx);
            ssc[tid * 33 + j] = e; sum += e;
        }
        float inv = 1.0f / sum;
        for (int j = 0; j < 32; j++)
            attn[(size_t)b * SS * SS + tid * 32 + j] = ssc[tid * 33 + j] * inv;
    }
}

// ---------------------------------------------------------------------------
// classifier scalar + softmax halves -> d_a/d_v (out tail + scratch)
// ---------------------------------------------------------------------------
__global__ __launch_bounds__(512)
void cls_head_kernel(const float* __restrict__ h, const float* __restrict__ w2,
                     const float* __restrict__ b2, float* __restrict__ dav,
                     float* __restrict__ out_d)
{
    int b = blockIdx.x;
    __shared__ float sd[32];
    int w = threadIdx.x >> 5, lane = threadIdx.x & 31;
    for (int s = w; s < SS; s += 16) {
        const float* hr = h + ((size_t)b * SS + s) * HH;
        const float* wr = w2 + (size_t)s * HH;
        float acc = 0.0f;
        for (int k = lane; k < HH; k += 32) acc += hr[k] * wr[k];
#pragma unroll
        for (int o = 16; o; o >>= 1) acc += __shfl_down_sync(0xffffffffu, acc, o);
        if (lane == 0) sd[s] = fmaxf(acc + b2[s], 0.0f);
    }
    __syncthreads();
    if (threadIdx.x < 2) {
        int off = threadIdx.x * PP;
        float mx = -1e30f;
        for (int j = 0; j < PP; j++) mx = fmaxf(mx, sd[off + j]);
        float sum = 0.0f;
        float e[PP];
        for (int j = 0; j < PP; j++) { e[j] = expf(sd[off + j] - mx); sum += e[j]; }
        float inv = 1.0f / sum;
        float* outp = out_d + (size_t)threadIdx.x * BB * PP + (size_t)b * PP;
        for (int j = 0; j < PP; j++) {
            float val = e[j] * inv;
            dav[b * SS + off + j] = val;
            outp[j] = val;
        }
    }
}

// ---------------------------------------------------------------------------
// mix in q-space: wa[t]=sum_s d_a[s]attn[s,t]; avmix_a[b]=sum_t wa[t] q[b,t,:]
// ---------------------------------------------------------------------------
__global__ __launch_bounds__(128)
void combine_kernel(const float* __restrict__ attn, const float* __restrict__ q,
                    const float* __restrict__ dav, float* __restrict__ avmix)
{
    int b = blockIdx.x;
    __shared__ float sat[SS * SS];
    __shared__ float wa[SS], wvv[SS];
    int tid = threadIdx.x;
    for (int i = tid; i < SS * SS; i += 128) sat[i] = attn[(size_t)b * SS * SS + i];
    __syncthreads();
    if (tid < SS) {
        float a = 0.0f, v = 0.0f;
        for (int s = 0; s < PP; s++) {
            a += dav[b * SS + s]      * sat[s * SS + tid];
            v += dav[b * SS + PP + s] * sat[(PP + s) * SS + tid];
        }
        wa[tid] = a; wvv[tid] = v;
    }
    __syncthreads();
    const float* qb = q + (size_t)b * SS * DD;
    for (int d = tid; d < DD; d += 128) {
        float a = 0.0f, v = 0.0f;
#pragma unroll
        for (int t = 0; t < SS; t++) {
            float x = qb[(size_t)t * DD + d];
            a += wa[t] * x;
            v += wvv[t] * x;
        }
        avmix[(size_t)b * DD + d] = a;
        avmix[((size_t)BB + b) * DD + d] = v;
    }
}

// fusion = 0.5*(audio+video)
__global__ void avg_kernel(float* __restrict__ fav)
{
    size_t i = (size_t)blockIdx.x * 256 + threadIdx.x;
    fav[i] = 0.5f * (fav[(size_t)BB * DD + i] + fav[(size_t)2 * BB * DD + i]);
}

// ---------------------------------------------------------------------------
// LayerNorm(512) + ReLU per row
// ---------------------------------------------------------------------------
__global__ __launch_bounds__(128)
void ln_kernel(const float* __restrict__ x, const float* __restrict__ g,
               const float* __restrict__ be, float* __restrict__ out)
{
    int row = blockIdx.x;
    const float* xr = x + (size_t)row * FF;
    int tid = threadIdx.x;
    __shared__ float sm[4];
    float v[4];
    float s = 0.0f;
#pragma unroll
    for (int i = 0; i < 4; i++) { v[i] = xr[tid + 128 * i]; s += v[i]; }
#pragma unroll
    for (int o = 16; o; o >>= 1) s += __shfl_down_sync(0xffffffffu, s, o);
    if ((tid & 31) == 0) sm[tid >> 5] = s;
    __syncthreads();
    float mu = (sm[0] + sm[1] + sm[2] + sm[3]) * (1.0f / FF);
    __syncthreads();
    float qv = 0.0f;
#pragma unroll
    for (int i = 0; i < 4; i++) { float d = v[i] - mu; qv += d * d; }
#pragma unroll
    for (int o = 16; o; o >>= 1) qv += __shfl_down_sync(0xffffffffu, qv, o);
    if ((tid & 31) == 0) sm[tid >> 5] = qv;
    __syncthreads();
    float var = (sm[0] + sm[1] + sm[2] + sm[3]) * (1.0f / FF);
    float rstd = rsqrtf(var + 1e-5f);
    float* orow = out + (size_t)row * FF;
#pragma unroll
    for (int i = 0; i < 4; i++) {
        int c = tid + 128 * i;
        float y = (v[i] - mu) * rstd * g[c] + be[c];
        orow[c] = fmaxf(y, 0.0f);
    }
}

// ---------------------------------------------------------------------------
extern "C" void kernel_launch(void* const* d_in, const int* in_sizes, int n_in,
                              void* d_out, int out_size)
{
    const float* q      = (const float*)d_in[0];
    const float* in_w   = (const float*)d_in[1];
    const float* in_b   = (const float*)d_in[2];
    const float* out_w  = (const float*)d_in[3];
    const float* out_b  = (const float*)d_in[4];
    const float* cls_w1 = (const float*)d_in[5];
    const float* cls_b1 = (const float*)d_in[6];
    const float* cls_w2 = (const float*)d_in[7];
    const float* cls_b2 = (const float*)d_in[8];
    const float* fus_w  = (const float*)d_in[9];
    const float* fus_b  = (const float*)d_in[10];
    const float* fus_g  = (const float*)d_in[11];
    const float* fus_be = (const float*)d_in[12];
    const float* pa_w   = (const float*)d_in[13];
    const float* pa_b   = (const float*)d_in[14];
    const float* pa_g   = (const float*)d_in[15];
    const float* pa_be  = (const float*)d_in[16];
    const float* pv_w   = (const float*)d_in[17];
    const float* pv_b   = (const float*)d_in[18];
    const float* pv_g   = (const float*)d_in[19];
    const float* pv_be  = (const float*)d_in[20];
    float* out = (float*)d_out;

    float* sp = nullptr;
    cudaGetSymbolAddress((void**)&sp, g_scratch);

    float* t1    = sp + OF_T1;
    float* h     = sp + OF_H;
    float* attn  = sp + OF_ATTN;
    float* dav   = sp + OF_DAV;
    float* avmix = sp + OF_AVMIX;
    float* avpre = sp + OF_AVPRE;
    float* fav   = sp + OF_FAV;
    float* headb = sp + OF_HEAD;
    float* Mt    = sp + OF_MT;
    float* WqT   = sp + OF_WT;
    float* WkT   = sp + OF_WT + (size_t)DD * DD;
    float* wv    = sp + OF_WV;

    const float* wv_w = in_w + (size_t)2 * DD * DD;
    const float* bv = in_b + 2 * DD;

    // 1. WqT, WkT transposes
    tr1024<<<dim3(32, 32, 2), dim3(32, 8)>>>(in_w, WqT);
    // 2. bias fold
    vec_kernel<<<4, 256>>>(in_w, in_b, wv);
    // 3. Mt[n,k] = sum_e WkT[n,e]*WqT[k,e]   (bf16 3-pass, full precision)
    mma_gemm<<<dim3(8, 8, 1), 256>>>(WkT, DD, 0, WqT, DD, 0, nullptr, 0,
                                     Mt, DD, 0, DD, 0);
    // 4. t1 = q @ M   (tf32, ldmatrix)
    tf32_gemm<<<dim3(8, 512, 1), 256>>>(q, DD, 0, Mt, DD, 0, nullptr, 0,
                                        t1, DD, 0, DD, 0);
    // 5. h = relu(q @ W1[s]^T + b1[s])   (tf32, ldmatrix)
    tf32_gemm<<<dim3(4, 16, 32), 256>>>(q, SS * DD, DD,
                                        cls_w1, DD, (long long)HH * DD,
                                        cls_b1, HH, h, SS * HH, HH, DD, 1);
    // 6. attention softmax (fused gv)
    attn_kernel<<<BB, 256>>>(q, t1, wv, attn);
    // 7. classifier head -> dav + out tail
    cls_head_kernel<<<BB, 512>>>(h, cls_w2, cls_b2, dav, out + (size_t)3 * BB * FF);
    // 8. q-space mix
    combine_kernel<<<BB, 128>>>(attn, q, dav, avmix);
    // 9. avpre = avmix @ Wv^T + bv   (bf16 3-pass)
    mma_gemm<<<dim3(8, 32, 1), 256>>>(avmix, DD, 0, wv_w, DD, 0, bv, 0,
                                      avpre, DD, 0, DD, 0);
    // 10. audio/video = avpre @ out_w^T + out_b -> fav[B..3B)   (bf16 3-pass)
    mma_gemm<<<dim3(8, 32, 1), 256>>>(avpre, DD, 0, out_w, DD, 0, out_b, 0,
                                      fav + (size_t)BB * DD, DD, 0, DD, 0);
    // 11. fusion
    avg_kernel<<<(BB * DD) / 256, 256>>>(fav);
    // 12-14. projector heads   (bf16 3-pass)
    mma_gemm<<<dim3(4, 16, 1), 256>>>(fav, DD, 0, fus_w, DD, 0, fus_b, 0,
                                      headb, FF, 0, DD, 0);
    mma_gemm<<<dim3(4, 16, 1), 256>>>(fav + (size_t)BB * DD, DD, 0, pa_w, DD, 0,
                                      pa_b, 0, headb + (size_t)BB * FF, FF, 0, DD, 0);
    mma_gemm<<<dim3(4, 16, 1), 256>>>(fav + (size_t)2 * BB * DD, DD, 0, pv_w, DD, 0,
                                      pv_b, 0, headb + (size_t)2 * BB * FF, FF, 0, DD, 0);
    // 15-17. LayerNorm + ReLU
    ln_kernel<<<BB, 128>>>(headb, fus_g, fus_be, out);
    ln_kernel<<<BB, 128>>>(headb + (size_t)BB * FF, pa_g, pa_be, out + (size_t)BB * FF);
    ln_kernel<<<BB, 128>>>(headb + (size_t)2 * BB * FF, pv_g, pv_be, out + (size_t)2 * BB * FF);
}